// round 1
// baseline (speedup 1.0000x reference)
#include <cuda_runtime.h>
#include <math_constants.h>

// Problem constants (fixed shapes from reference setup_inputs)
#define NB 64
#define NA 5
#define NC 20
#define NH 38
#define NW 38
#define HW (NH*NW)            // 1444
#define MAXB 50
#define CELLS_PER_B (NA*HW)   // 7220

__constant__ float c_aw[5] = {1.3221f, 3.19275f, 5.05587f, 9.47112f, 11.2364f};
__constant__ float c_ah[5] = {1.73145f, 4.00944f, 8.09892f, 4.84053f, 10.0071f};

// Device scratch (no allocations allowed)
__device__ int    g_assign[NB*CELLS_PER_B];   // winning box index per cell, -1 if none
__device__ float4 g_ioubox[NB*MAXB];          // (xlo, xhi, ylo, yhi) of GT box
__device__ float  g_cg[NB*MAXB];              // 0.375*areaG, +inf if invalid box
__device__ float4 g_tgtA[NB*MAXB];            // tx_v, ty_v, tw_v, th_v
__device__ float4 g_tgtB[NB*MAXB];            // iou_gt (tconf), gcls, 0, 0
__device__ double g_loss;

__device__ __forceinline__ float sigmoidf_(float v){ return 1.0f/(1.0f+expf(-v)); }

__device__ __forceinline__ float iou_full(float x1,float y1,float w1,float h1,
                                          float x2,float y2,float w2,float h2){
  float uw = fmaxf(x1+0.5f*w1, x2+0.5f*w2) - fminf(x1-0.5f*w1, x2-0.5f*w2);
  float uh = fmaxf(y1+0.5f*h1, y2+0.5f*h2) - fminf(y1-0.5f*h1, y2-0.5f*h2);
  float cw = w1+w2-uw, ch = h1+h2-uh;
  float inter = (cw<=0.f || ch<=0.f) ? 0.f : cw*ch;
  return inter/(w1*h1 + w2*h2 - inter);
}

// ---------------------------------------------------------------------------
// Kernel 1: per-batch GT prep + assignment map reset/build. 64 blocks x 64 thr.
// ---------------------------------------------------------------------------
__global__ void prep_kernel(const float* __restrict__ out, const float* __restrict__ tgt){
  int b = blockIdx.x, tid = threadIdx.x;

  // reset this batch's assignment region
  for (int k = tid; k < CELLS_PER_B; k += blockDim.x) g_assign[b*CELLS_PER_B + k] = -1;
  if (b == 0 && tid == 0) g_loss = 0.0;

  __shared__ int s_xnz[MAXB];
  __shared__ int s_cell[MAXB];
  __shared__ int s_valid[MAXB];

  float gcls = 0.f, gx = 0.f, gy = 0.f, gw = 0.f, gh = 0.f;
  if (tid < MAXB){
    const float* p = tgt + b*(MAXB*5) + tid*5;
    gcls = p[0];
    float xn = p[1], yn = p[2], wn = p[3], hn = p[4];
    s_xnz[tid] = (xn != 0.0f) ? 1 : 0;
    gx = xn*(float)NW; gy = yn*(float)NH; gw = wn*(float)NW; gh = hn*(float)NH;
  }
  __syncthreads();

  if (tid < MAXB){
    // cumulative validity (cumprod of x!=0)
    int valid = 1;
    for (int q = 0; q <= tid; ++q) valid &= s_xnz[q];

    // best anchor by wh-IoU (argmax, first-max wins)
    int best = 0; float bestv = -1.0f;
    #pragma unroll
    for (int a = 0; a < NA; ++a){
      float v = iou_full(0.f,0.f,gw,gh, 0.f,0.f,c_aw[a],c_ah[a]);
      if (v > bestv){ bestv = v; best = a; }
    }

    int gi = min(max((int)gx, 0), NW-1);
    int gj = min(max((int)gy, 0), NH-1);
    float txv = gx - (float)gi, tyv = gy - (float)gj;
    float twv = logf(gw / c_aw[best]), thv = logf(gh / c_ah[best]);

    // pred box at the assigned cell (pre-scan pred_boxes)
    int base = ((b*NA + best)*25)*HW + gj*NW + gi;
    float px = sigmoidf_(out[base])        + (float)gi;
    float py = sigmoidf_(out[base + HW])   + (float)gj;
    float pw = expf(out[base + 2*HW]) * c_aw[best];
    float ph = expf(out[base + 3*HW]) * c_ah[best];
    float ig = iou_full(gx,gy,gw,gh, px,py,pw,ph);

    int o = b*MAXB + tid;
    g_ioubox[o] = make_float4(gx-0.5f*gw, gx+0.5f*gw, gy-0.5f*gh, gy+0.5f*gh);
    g_cg[o]     = valid ? 0.375f*gw*gh : CUDART_INF_F;
    g_tgtA[o]   = make_float4(txv, tyv, twv, thv);
    g_tgtB[o]   = make_float4(ig, gcls, 0.f, 0.f);
    s_cell[tid]  = best*HW + gj*NW + gi;
    s_valid[tid] = valid;
  }
  __syncthreads();

  // sequential scatter: later valid boxes overwrite earlier (scan semantics)
  if (tid == 0){
    for (int t = 0; t < MAXB; ++t)
      if (s_valid[t]) g_assign[b*CELLS_PER_B + s_cell[t]] = t;
  }
}

// ---------------------------------------------------------------------------
// Kernel 2: main loss. Block = one (batch, grid-row): 5 anchors x 38 cols.
// ---------------------------------------------------------------------------
__global__ void __launch_bounds__(192) main_kernel(const float* __restrict__ out){
  int b = blockIdx.y, j = blockIdx.x, tid = threadIdx.x;

  __shared__ float4 s_cbox[MAXB];
  __shared__ float  s_ccg[MAXB];
  __shared__ int    s_cnt;
  __shared__ float  s_wsum[6];

  if (tid == 0) s_cnt = 0;
  __syncthreads();

  // row-pruned candidate boxes: iou>0.6 requires |gy-(j+0.5)| <= 0.5 + (2/3)gh
  if (tid < MAXB){
    float4 q = g_ioubox[b*MAXB + tid];
    float cg = g_cg[b*MAXB + tid];
    float gyc = 0.5f*(q.z + q.w);
    float ghh = q.w - q.z;
    if (cg < CUDART_INF_F &&
        fabsf(gyc - ((float)j + 0.5f)) <= 0.5f + 0.6666667f*ghh + 1e-3f){
      int idx = atomicAdd(&s_cnt, 1);
      s_cbox[idx] = q; s_ccg[idx] = cg;
    }
  }
  __syncthreads();

  int n = s_cnt;
  float lsum = 0.0f;

  if (tid < NA*NW){
    int a = tid / NW, i = tid % NW;
    int base = ((b*NA + a)*25)*HW + j*NW + i;

    float o0 = out[base];
    float o1 = out[base +   HW];
    float o2 = out[base + 2*HW];
    float o3 = out[base + 3*HW];
    float o4 = out[base + 4*HW];

    float x = sigmoidf_(o0), y = sigmoidf_(o1);
    float w = o2, h = o3;
    float conf = sigmoidf_(o4);

    float pw = expf(w)*c_aw[a], ph = expf(h)*c_ah[a];
    float px = x + (float)i,    py = y + (float)j;
    float xlo = px - 0.5f*pw, xhi = px + 0.5f*pw;
    float ylo = py - 0.5f*ph, yhi = py + 0.5f*ph;
    float cp = 0.375f*pw*ph;

    // any GT box with iou > 0.6 ?  (division-free: inter > 0.375*(areaP+areaG))
    int over = 0;
    for (int t = 0; t < n; ++t){
      float4 q = s_cbox[t];
      float cw = fminf(xhi, q.y) - fmaxf(xlo, q.x);
      float ch = fminf(yhi, q.w) - fmaxf(ylo, q.z);
      cw = fmaxf(cw, 0.f); ch = fmaxf(ch, 0.f);
      over |= (cw*ch > cp + s_ccg[t]);
    }

    float tx = 0.5f, ty = 0.5f, tw = 0.f, th = 0.f, tconf = 0.f;
    float cscale = over ? 0.f : 1.f;   // NOOBJECT_SCALE=1, silenced=0

    int t = g_assign[b*CELLS_PER_B + a*HW + j*NW + i];
    if (t >= 0){
      float4 A = g_tgtA[b*MAXB + t];
      float4 B = g_tgtB[b*MAXB + t];
      tx = A.x; ty = A.y; tw = A.z; th = A.w;
      tconf = B.x; cscale = 5.0f;     // OBJECT_SCALE
      int label = (int)B.y;
      // class cross-entropy (only at assigned cells): log(sum exp) - logit[label]
      float se = 0.f, lsel = 0.f;
      #pragma unroll
      for (int c = 0; c < NC; ++c){
        float l = out[base + (5+c)*HW];
        se += expf(l);
        if (c == label) lsel = l;
      }
      lsum += logf(se) - lsel;
    }

    float dx = x - tx, dy = y - ty, dw = w - tw, dh = h - th, dc = conf - tconf;
    lsum += 0.5f*(dx*dx + dy*dy + dw*dw + dh*dh) + 0.5f*cscale*dc*dc;
  }

  // block reduction -> double atomic
  #pragma unroll
  for (int off = 16; off > 0; off >>= 1)
    lsum += __shfl_down_sync(0xffffffffu, lsum, off);
  if ((tid & 31) == 0) s_wsum[tid >> 5] = lsum;
  __syncthreads();
  if (tid == 0){
    float bs = 0.f;
    #pragma unroll
    for (int wi = 0; wi < 6; ++wi) bs += s_wsum[wi];
    atomicAdd(&g_loss, (double)bs);
  }
}

// ---------------------------------------------------------------------------
// Kernel 3: write scalar result
// ---------------------------------------------------------------------------
__global__ void fin_kernel(float* o){
  if (threadIdx.x == 0) o[0] = (float)g_loss;
}

extern "C" void kernel_launch(void* const* d_in, const int* in_sizes, int n_in,
                              void* d_out, int out_size){
  const float* outp = (const float*)d_in[0];
  const float* tgtp = (const float*)d_in[1];
  // defensive: metadata order is (output, target); swap if sizes disagree
  if (n_in >= 2 && in_sizes[0] < in_sizes[1]){
    const float* tmp = outp; outp = tgtp; tgtp = tmp;
  }
  prep_kernel<<<NB, 64>>>(outp, tgtp);
  main_kernel<<<dim3(NH, NB), 192>>>(outp);
  fin_kernel<<<1, 32>>>((float*)d_out);
}

// round 3
// speedup vs baseline: 1.1064x; 1.1064x over previous
#include <cuda_runtime.h>
#include <math_constants.h>

#define NB 64
#define NA 5
#define NC 20
#define NH 38
#define NW 38
#define HW (NH*NW)            // 1444
#define MAXB 50
#define RPB 2                 // grid rows per block
#define GX (NH/RPB)           // 19
#define TPB 384
#define CELLS_ROW (NA*NW)     // 190
#define NBLK (GX*NB)          // 1216

__constant__ float c_aw[5] = {1.3221f, 3.19275f, 5.05587f, 9.47112f, 11.2364f};
__constant__ float c_ah[5] = {1.73145f, 4.00944f, 8.09892f, 4.84053f, 10.0071f};

__device__ double        g_part[GX];   // zero at load; reset within each launch
__device__ unsigned long long g_ctr;   // monotonically increasing across replays

__device__ __forceinline__ float fsig(float v){
  return __fdividef(1.0f, 1.0f + __expf(-v));
}

// ---------------------------------------------------------------------------
// Single fused kernel. Block = (batch b, 2 grid rows j0..j0+1).
// Phase A (tid<50): per-GT-box prep (redundant per block, L2-cached loads).
// Phase B: per-cell loss; division-free conf silencing + compact assign list.
// Phase C: block reduce -> spread double atomics -> last-arriving block writes.
// g_ctr is never reset: "last" = (old % NBLK == NBLK-1). Robust across replays.
// ---------------------------------------------------------------------------
__global__ void __launch_bounds__(TPB) region_kernel(const float* __restrict__ out,
                                                     const float* __restrict__ tgt,
                                                     float* __restrict__ res){
  const int b  = blockIdx.y;
  const int j0 = blockIdx.x * RPB;
  const int tid = threadIdx.x;

  __shared__ float4 s_A[MAXB];      // tx, ty, tw, th targets per box
  __shared__ float2 s_B[MAXB];      // tconf (iou_gt), gcls
  __shared__ int    s_xnz[MAXB];
  __shared__ float4 s_cb[MAXB];     // conf-silencing candidates (xlo,xhi,ylo,yhi)
  __shared__ float  s_ccg[MAXB];    // 0.375*areaG per candidate
  __shared__ int    s_akey[MAXB];   // assignment list: cell key
  __shared__ int    s_at[MAXB];     // assignment list: box index t
  __shared__ int    s_nc, s_na, s_islast;
  __shared__ float  s_ws[TPB/32];

  if (tid == 0){ s_nc = 0; s_na = 0; }

  // ---- Phase A: GT box prep ----
  float gx=0.f, gy=0.f, gw=0.f, gh=0.f, gcls=0.f;
  if (tid < MAXB){
    const float* p = tgt + b*(MAXB*5) + tid*5;
    gcls = p[0];
    float xn = p[1];
    s_xnz[tid] = (xn != 0.0f) ? 1 : 0;
    gx = xn*(float)NW; gy = p[2]*(float)NH; gw = p[3]*(float)NW; gh = p[4]*(float)NH;
  }
  __syncthreads();

  if (tid < MAXB){
    int valid = 1;
    for (int q = 0; q <= tid; ++q) valid &= s_xnz[q];

    // division-free anchor argmax (first-max wins, matches argmax)
    int best = 0; float bi = -1.0f, bu = 1.0f;
    #pragma unroll
    for (int a = 0; a < NA; ++a){
      float inter = fminf(gw, c_aw[a]) * fminf(gh, c_ah[a]);
      float uni   = gw*gh + c_aw[a]*c_ah[a] - inter;
      if (inter*bu > bi*uni){ bi = inter; bu = uni; best = a; }
    }

    int gi = min(max((int)gx, 0), NW-1);
    int gj = min(max((int)gy, 0), NH-1);

    // pred box at assigned cell -> iou_gt (tconf)
    int base = ((b*NA + best)*25)*HW + gj*NW + gi;
    float px = fsig(out[base])        + (float)gi;
    float py = fsig(out[base + HW])   + (float)gj;
    float pw = __expf(out[base + 2*HW]) * c_aw[best];
    float ph = __expf(out[base + 3*HW]) * c_ah[best];
    float uw = fmaxf(gx+0.5f*gw, px+0.5f*pw) - fminf(gx-0.5f*gw, px-0.5f*pw);
    float uh = fmaxf(gy+0.5f*gh, py+0.5f*ph) - fminf(gy-0.5f*gh, py-0.5f*ph);
    float cw = gw+pw-uw, ch = gh+ph-uh;
    float inter = (cw <= 0.f || ch <= 0.f) ? 0.f : cw*ch;
    float ig = __fdividef(inter, gw*gh + pw*ph - inter);

    s_A[tid] = make_float4(gx - (float)gi, gy - (float)gj,
                           __logf(__fdividef(gw, c_aw[best])),
                           __logf(__fdividef(gh, c_ah[best])));
    s_B[tid] = make_float2(ig, gcls);

    // conf-silencing candidates, row-pruned for this block's 2 rows:
    // iou>0.6 => ch >= 0.6*gh and ch <= 1 (py within (j,j+1) row band)
    if (valid && fabsf(gy - ((float)j0 + 1.0f)) <= 1.0f + 0.6666667f*gh + 1e-3f){
      int u = atomicAdd(&s_nc, 1);
      s_cb[u]  = make_float4(gx-0.5f*gw, gx+0.5f*gw, gy-0.5f*gh, gy+0.5f*gh);
      s_ccg[u] = 0.375f*gw*gh;
    }
    // assignment list (last-valid-wins resolved by max-t at lookup)
    if (valid && (gj == j0 || gj == j0+1)){
      int u = atomicAdd(&s_na, 1);
      s_akey[u] = (best*NH + gj)*NW + gi;
      s_at[u]   = tid;
    }
  }
  __syncthreads();

  // ---- Phase B: per-cell loss ----
  float lsum = 0.0f;
  if (tid < RPB*CELLS_ROW){
    int r = tid / CELLS_ROW;
    int c = tid - r*CELLS_ROW;
    int a = c / NW, i = c - a*NW;
    int j = j0 + r;
    int base = ((b*NA + a)*25)*HW + j*NW + i;

    float o0 = out[base];
    float o1 = out[base +   HW];
    float o2 = out[base + 2*HW];
    float o3 = out[base + 3*HW];
    float o4 = out[base + 4*HW];

    float x = fsig(o0), y = fsig(o1), conf = fsig(o4);
    float pw = __expf(o2)*c_aw[a], ph = __expf(o3)*c_ah[a];
    float px = x + (float)i,       py = y + (float)j;
    float xlo = px - 0.5f*pw, xhi = px + 0.5f*pw;
    float ylo = py - 0.5f*ph, yhi = py + 0.5f*ph;
    float cp = 0.375f*pw*ph;

    // division-free silencing: iou>0.6 <=> inter > 0.375*(areaP+areaG)
    int over = 0, n = s_nc;
    for (int t = 0; t < n; ++t){
      float4 q = s_cb[t];
      float cw = fminf(xhi, q.y) - fmaxf(xlo, q.x);
      float ch = fminf(yhi, q.w) - fmaxf(ylo, q.z);
      over |= (fmaxf(cw, 0.f)*fmaxf(ch, 0.f) > cp + s_ccg[t]);
    }

    // assignment lookup: match with max t wins (scan semantics)
    int mykey = (a*NH + j)*NW + i;
    int tb = -1, na = s_na;
    for (int u = 0; u < na; ++u){
      int k = s_akey[u], tt = s_at[u];
      if (k == mykey && tt > tb) tb = tt;
    }

    float tx=0.5f, ty=0.5f, tw=0.f, th=0.f, tconf=0.f;
    float cscale = over ? 0.f : 1.f;           // NOOBJECT_SCALE=1, silenced=0
    if (tb >= 0){
      float4 A = s_A[tb]; float2 B = s_B[tb];
      tx = A.x; ty = A.y; tw = A.z; th = A.w;
      tconf = B.x; cscale = 5.0f;              // OBJECT_SCALE
      int label = (int)B.y;
      float se = 0.f, lsel = 0.f;
      #pragma unroll
      for (int cc = 0; cc < NC; ++cc){
        float l = out[base + (5+cc)*HW];
        se += __expf(l);
        if (cc == label) lsel = l;
      }
      lsum += __logf(se) - lsel;
    }

    float dx = x-tx, dy = y-ty, dw = o2-tw, dh = o3-th, dc = conf-tconf;
    lsum += 0.5f*(dx*dx + dy*dy + dw*dw + dh*dh) + 0.5f*cscale*dc*dc;
  }

  // ---- Phase C: reduce + finalize ----
  #pragma unroll
  for (int off = 16; off > 0; off >>= 1)
    lsum += __shfl_down_sync(0xffffffffu, lsum, off);
  if ((tid & 31) == 0) s_ws[tid >> 5] = lsum;
  __syncthreads();

  if (tid == 0){
    float bs = 0.f;
    #pragma unroll
    for (int wv = 0; wv < TPB/32; ++wv) bs += s_ws[wv];
    atomicAdd(&g_part[blockIdx.x], (double)bs);
    __threadfence();
    unsigned long long v = atomicAdd(&g_ctr, 1ull);
    s_islast = ((v % (unsigned long long)NBLK) == (unsigned long long)(NBLK - 1)) ? 1 : 0;
  }
  __syncthreads();

  // Last-arriving block: every other block has completed its atomics (they
  // incremented g_ctr after a threadfence). Read, write result, zero slots.
  if (s_islast && tid == 0){
    __threadfence();
    double tot = 0.0;
    for (int q = 0; q < GX; ++q){
      // atomicExch returns the accumulated value and zeroes the slot in one
      // step, keeping read+reset atomic w.r.t. any future launch.
      unsigned long long old = atomicExch((unsigned long long*)&g_part[q], 0ull);
      tot += __longlong_as_double((long long)old);
    }
    res[0] = (float)tot;
  }
}

extern "C" void kernel_launch(void* const* d_in, const int* in_sizes, int n_in,
                              void* d_out, int out_size){
  const float* outp = (const float*)d_in[0];
  const float* tgtp = (const float*)d_in[1];
  if (n_in >= 2 && in_sizes[0] < in_sizes[1]){
    const float* tmp = outp; outp = tgtp; tgtp = tmp;
  }
  region_kernel<<<dim3(GX, NB), TPB>>>(outp, tgtp, (float*)d_out);
}

// round 4
// speedup vs baseline: 1.3450x; 1.2156x over previous
#include <cuda_runtime.h>
#include <math_constants.h>

#define NB 64
#define NA 5
#define NC 20
#define NH 38
#define NW 38
#define HW (NH*NW)            // 1444
#define MAXB 50
#define RPB 2                 // grid rows per block
#define GX (NH/RPB)           // 19
#define TPB 192
#define CELLS_ROW (NA*NW)     // 190
#define NCELL (RPB*CELLS_ROW) // 380
#define NBLK (GX*NB)          // 1216

__constant__ float c_aw[5] = {1.3221f, 3.19275f, 5.05587f, 9.47112f, 11.2364f};
__constant__ float c_ah[5] = {1.73145f, 4.00944f, 8.09892f, 4.84053f, 10.0071f};

__device__ double             g_part[GX];
__device__ unsigned long long g_ctr;     // monotone across replays, never reset

__device__ __forceinline__ float fsig(float v){
  return __fdividef(1.0f, 1.0f + __expf(-v));
}

// ---------------------------------------------------------------------------
// One fused kernel. Block = (batch b, rows j0..j0+1). 192 thr, 2 cells/thread.
// Pre-barrier: tgt load + ballot validity + Phase-B LDG prefetch (latency hides
// under Phase A). Phase A (tid<50): targets, iou_gt, pruned candidate list
// (|gy-(j0+1)| < 1 + 0.4*gh), compact assignment list. Phase B: fused 2-cell
// loops over shared lists. Finalize: spread double atomics + last-block write.
// ---------------------------------------------------------------------------
__global__ void __launch_bounds__(TPB) region_kernel(const float* __restrict__ out,
                                                     const float* __restrict__ tgt,
                                                     float* __restrict__ res){
  const int b   = blockIdx.y;
  const int j0  = blockIdx.x * RPB;
  const int tid = threadIdx.x;

  __shared__ float4 s_A[MAXB];      // tx, ty, tw, th
  __shared__ float2 s_B[MAXB];      // tconf(iou_gt), gcls
  __shared__ float4 s_cb[MAXB];     // candidates (xlo,xhi,ylo,yhi)
  __shared__ float  s_ccg[MAXB];    // 0.375*areaG
  __shared__ int    s_akey[MAXB];
  __shared__ int    s_at[MAXB];
  __shared__ int    s_nc, s_na, s_w0all, s_islast;
  __shared__ float  s_ws[TPB/32];

  if (tid == 0){ s_nc = 0; s_na = 0; }

  // ---- tgt load + ballot prefix-AND validity ----
  float gcls=0.f, gx=0.f, gy=0.f, gw=0.f, gh=0.f, xn=1.0f;
  if (tid < MAXB){
    const float* p = tgt + b*(MAXB*5) + tid*5;
    gcls = p[0]; xn = p[1];
    gx = xn*(float)NW; gy = p[2]*(float)NH; gw = p[3]*(float)NW; gh = p[4]*(float)NH;
  }
  unsigned msk  = __ballot_sync(0xffffffffu, xn != 0.0f);
  int      lane = tid & 31;
  unsigned need = 0xffffffffu >> (31 - lane);
  int      pre  = ((msk & need) == need);
  if (tid == 0) s_w0all = (msk == 0xffffffffu);

  // ---- Phase-B prefetch (10 LDGs issued before the barrier) ----
  const int c0 = tid;
  const int c1raw = tid + TPB;
  const bool has1 = (c1raw < NCELL);
  const int c1 = has1 ? c1raw : c0;

  int r0 = c0 / CELLS_ROW, q0 = c0 - r0*CELLS_ROW;
  int a0 = q0 / NW,        i0 = q0 - a0*NW,  jj0 = j0 + r0;
  int r1 = c1 / CELLS_ROW, q1 = c1 - r1*CELLS_ROW;
  int a1 = q1 / NW,        i1 = q1 - a1*NW,  jj1 = j0 + r1;
  const int base0 = ((b*NA + a0)*25)*HW + jj0*NW + i0;
  const int base1 = ((b*NA + a1)*25)*HW + jj1*NW + i1;

  float p00 = out[base0],        p10 = out[base1];
  float p01 = out[base0 +   HW], p11 = out[base1 +   HW];
  float p02 = out[base0 + 2*HW], p12 = out[base1 + 2*HW];
  float p03 = out[base0 + 3*HW], p13 = out[base1 + 3*HW];
  float p04 = out[base0 + 4*HW], p14 = out[base1 + 4*HW];

  __syncthreads();   // publish s_w0all; s_nc/s_na init complete

  // ---- Phase A: per-GT-box prep ----
  if (tid < MAXB){
    int valid = (tid < 32) ? pre : (pre & s_w0all);

    // division-free anchor argmax (first-max wins)
    int best = 0; float bi = -1.0f, bu = 1.0f;
    #pragma unroll
    for (int a = 0; a < NA; ++a){
      float inter = fminf(gw, c_aw[a]) * fminf(gh, c_ah[a]);
      float uni   = gw*gh + c_aw[a]*c_ah[a] - inter;
      if (inter*bu > bi*uni){ bi = inter; bu = uni; best = a; }
    }

    int gi = min(max((int)gx, 0), NW-1);
    int gj = min(max((int)gy, 0), NH-1);

    int base = ((b*NA + best)*25)*HW + gj*NW + gi;
    float px = fsig(out[base])        + (float)gi;
    float py = fsig(out[base + HW])   + (float)gj;
    float pw = __expf(out[base + 2*HW]) * c_aw[best];
    float ph = __expf(out[base + 3*HW]) * c_ah[best];
    float uw = fmaxf(gx+0.5f*gw, px+0.5f*pw) - fminf(gx-0.5f*gw, px-0.5f*pw);
    float uh = fmaxf(gy+0.5f*gh, py+0.5f*ph) - fminf(gy-0.5f*gh, py-0.5f*ph);
    float cw = gw+pw-uw, ch = gh+ph-uh;
    float inter = (cw <= 0.f || ch <= 0.f) ? 0.f : cw*ch;
    float ig = __fdividef(inter, gw*gh + pw*ph - inter);

    s_A[tid] = make_float4(gx - (float)gi, gy - (float)gj,
                           __logf(__fdividef(gw, c_aw[best])),
                           __logf(__fdividef(gh, c_ah[best])));
    s_B[tid] = make_float2(ig, gcls);

    // candidates: iou>0.6 requires |gy-(row+0.5)| < 0.5 + 0.4*gh (exact bound,
    // maximized over feasible pred heights); band of 2 rows -> center j0+1.
    if (valid && fabsf(gy - ((float)j0 + 1.0f)) <= 1.0f + 0.4001f*gh + 1e-3f){
      int u = atomicAdd(&s_nc, 1);
      s_cb[u]  = make_float4(gx-0.5f*gw, gx+0.5f*gw, gy-0.5f*gh, gy+0.5f*gh);
      s_ccg[u] = 0.375f*gw*gh;
    }
    if (valid && (gj == j0 || gj == j0+1)){
      int u = atomicAdd(&s_na, 1);
      s_akey[u] = (best*NH + gj)*NW + gi;
      s_at[u]   = tid;
    }
  }
  __syncthreads();

  // ---- Phase B: two cells per thread, fused shared-list loops ----
  float x0 = fsig(p00), y0 = fsig(p01), cf0 = fsig(p04);
  float x1 = fsig(p10), y1 = fsig(p11), cf1 = fsig(p14);
  float pw0 = __expf(p02)*c_aw[a0], ph0 = __expf(p03)*c_ah[a0];
  float pw1 = __expf(p12)*c_aw[a1], ph1 = __expf(p13)*c_ah[a1];
  float px0 = x0 + (float)i0, py0 = y0 + (float)jj0;
  float px1 = x1 + (float)i1, py1 = y1 + (float)jj1;
  float xl0 = px0-0.5f*pw0, xh0 = px0+0.5f*pw0, yl0 = py0-0.5f*ph0, yh0 = py0+0.5f*ph0;
  float xl1 = px1-0.5f*pw1, xh1 = px1+0.5f*pw1, yl1 = py1-0.5f*ph1, yh1 = py1+0.5f*ph1;
  float cp0 = 0.375f*pw0*ph0, cp1 = 0.375f*pw1*ph1;

  int ov0 = 0, ov1 = 0;
  const int n = s_nc;
  for (int t = 0; t < n; ++t){
    float4 qq = s_cb[t];
    float  cg = s_ccg[t];
    float cw0 = fminf(xh0, qq.y) - fmaxf(xl0, qq.x);
    float chh0= fminf(yh0, qq.w) - fmaxf(yl0, qq.z);
    ov0 |= (fmaxf(cw0,0.f)*fmaxf(chh0,0.f) > cp0 + cg);
    float cw1 = fminf(xh1, qq.y) - fmaxf(xl1, qq.x);
    float chh1= fminf(yh1, qq.w) - fmaxf(yl1, qq.z);
    ov1 |= (fmaxf(cw1,0.f)*fmaxf(chh1,0.f) > cp1 + cg);
  }

  const int key0 = (a0*NH + jj0)*NW + i0;
  const int key1 = (a1*NH + jj1)*NW + i1;
  int tb0 = -1, tb1 = -1;
  const int na = s_na;
  for (int u = 0; u < na; ++u){
    int k = s_akey[u], tt = s_at[u];
    if (k == key0 && tt > tb0) tb0 = tt;
    if (k == key1 && tt > tb1) tb1 = tt;
  }

  float lsum = 0.0f;
  {
    float tx=0.5f, ty=0.5f, tw=0.f, th=0.f, tcf=0.f;
    float cs = ov0 ? 0.f : 1.f;
    if (tb0 >= 0){
      float4 A = s_A[tb0]; float2 B = s_B[tb0];
      tx=A.x; ty=A.y; tw=A.z; th=A.w; tcf=B.x; cs=5.0f;
      int label = (int)B.y;
      float se=0.f, lsel=0.f;
      #pragma unroll
      for (int cc = 0; cc < NC; ++cc){
        float l = out[base0 + (5+cc)*HW];
        se += __expf(l);
        if (cc == label) lsel = l;
      }
      lsum += __logf(se) - lsel;
    }
    float dx=x0-tx, dy=y0-ty, dw=p02-tw, dh=p03-th, dc=cf0-tcf;
    lsum += 0.5f*(dx*dx + dy*dy + dw*dw + dh*dh) + 0.5f*cs*dc*dc;
  }
  if (has1){
    float tx=0.5f, ty=0.5f, tw=0.f, th=0.f, tcf=0.f;
    float cs = ov1 ? 0.f : 1.f;
    if (tb1 >= 0){
      float4 A = s_A[tb1]; float2 B = s_B[tb1];
      tx=A.x; ty=A.y; tw=A.z; th=A.w; tcf=B.x; cs=5.0f;
      int label = (int)B.y;
      float se=0.f, lsel=0.f;
      #pragma unroll
      for (int cc = 0; cc < NC; ++cc){
        float l = out[base1 + (5+cc)*HW];
        se += __expf(l);
        if (cc == label) lsel = l;
      }
      lsum += __logf(se) - lsel;
    }
    float dx=x1-tx, dy=y1-ty, dw=p12-tw, dh=p13-th, dc=cf1-tcf;
    lsum += 0.5f*(dx*dx + dy*dy + dw*dw + dh*dh) + 0.5f*cs*dc*dc;
  }

  // ---- reduce + finalize ----
  #pragma unroll
  for (int off = 16; off > 0; off >>= 1)
    lsum += __shfl_down_sync(0xffffffffu, lsum, off);
  if (lane == 0) s_ws[tid >> 5] = lsum;
  __syncthreads();

  if (tid == 0){
    float bs = 0.f;
    #pragma unroll
    for (int wv = 0; wv < TPB/32; ++wv) bs += s_ws[wv];
    atomicAdd(&g_part[blockIdx.x], (double)bs);
    __threadfence();
    unsigned long long v = atomicAdd(&g_ctr, 1ull);
    s_islast = ((v % (unsigned long long)NBLK) == (unsigned long long)(NBLK-1)) ? 1 : 0;
  }
  __syncthreads();

  if (s_islast && tid == 0){
    __threadfence();
    double tot = 0.0;
    for (int q = 0; q < GX; ++q){
      unsigned long long old = atomicExch((unsigned long long*)&g_part[q], 0ull);
      tot += __longlong_as_double((long long)old);
    }
    res[0] = (float)tot;
  }
}

extern "C" void kernel_launch(void* const* d_in, const int* in_sizes, int n_in,
                              void* d_out, int out_size){
  const float* outp = (const float*)d_in[0];
  const float* tgtp = (const float*)d_in[1];
  if (n_in >= 2 && in_sizes[0] < in_sizes[1]){
    const float* tmp = outp; outp = tgtp; tgtp = tmp;
  }
  region_kernel<<<dim3(GX, NB), TPB>>>(outp, tgtp, (float*)d_out);
}